// round 2
// baseline (speedup 1.0000x reference)
#include <cuda_runtime.h>

#define FULL 0xFFFFFFFFu

constexpr int DM  = 64;    // model dim
constexpr int NC  = 128;   // 2 heads * 64
constexpr int DEG = 8;
constexpr int MAXN = 100000;

// Scratch (static device arrays; no allocation at runtime)
__device__ float g_G[DM * NC];     // G[d][col], col = h*64 + e : M_h[d][e]
__device__ float g_v[NC];          // v[h*64+e] = sum_t B_h[t][e] * bq_h[t]
__device__ float g_Z[MAXN * NC];   // y: Z[node][h*64+e] = sum_d x[node][d] * M_h[d][e]

// ---------------------------------------------------------------------------
// Prologue: M_h = A_h^T B_h  (64x64 per head), v_h = B_h^T bq_h.
// A_h[t][d] = W[(h*192+t)*64 + d]   (q weights)
// B_h[t][e] = W[(h*192+64+t)*64+e]  (k weights)
// ---------------------------------------------------------------------------
__global__ void __launch_bounds__(256) prologue_kernel(const float* __restrict__ W,
                                                       const float* __restrict__ b) {
    const int h = blockIdx.x;  // 0..1
    __shared__ float As[64][64];
    __shared__ float Bs[64][64];
    const int tid = threadIdx.x;

    const float4* Wq = (const float4*)(W + (h * 192) * 64);
    const float4* Wk = (const float4*)(W + (h * 192 + 64) * 64);
    float4* As4 = (float4*)As;
    float4* Bs4 = (float4*)Bs;
    for (int i = tid; i < 64 * 16; i += 256) {
        As4[i] = Wq[i];
        Bs4[i] = Wk[i];
    }
    __syncthreads();

    // 4x4 micro-tile per thread: 4096 outputs / 256 threads
    const int e0 = (tid & 15) * 4;
    const int d0 = (tid >> 4) * 4;
    float acc[4][4] = {};
#pragma unroll 8
    for (int t = 0; t < 64; t++) {
        float4 a = *(const float4*)&As[t][d0];
        float4 bv = *(const float4*)&Bs[t][e0];
        acc[0][0] += a.x * bv.x; acc[0][1] += a.x * bv.y; acc[0][2] += a.x * bv.z; acc[0][3] += a.x * bv.w;
        acc[1][0] += a.y * bv.x; acc[1][1] += a.y * bv.y; acc[1][2] += a.y * bv.z; acc[1][3] += a.y * bv.w;
        acc[2][0] += a.z * bv.x; acc[2][1] += a.z * bv.y; acc[2][2] += a.z * bv.z; acc[2][3] += a.z * bv.w;
        acc[3][0] += a.w * bv.x; acc[3][1] += a.w * bv.y; acc[3][2] += a.w * bv.z; acc[3][3] += a.w * bv.w;
    }
#pragma unroll
    for (int di = 0; di < 4; di++)
#pragma unroll
        for (int ei = 0; ei < 4; ei++)
            g_G[(d0 + di) * NC + h * 64 + e0 + ei] = acc[di][ei];

    // v_h[e] = sum_t B_h[t][e] * b[h*192 + t]
    if (tid < 64) {
        float s = 0.0f;
#pragma unroll 8
        for (int t = 0; t < 64; t++) s += Bs[t][tid] * b[h * 192 + t];
        g_v[h * 64 + tid] = s;
    }
}

// ---------------------------------------------------------------------------
// GEMM: Z[n][128] = x[n][64] @ G[64][128], split into two 64-col halves
// (blockIdx.y) so smem fits 48KB static. Tile: 128 rows x 64 cols / block,
// 256 threads, 8x4 outputs per thread.
// ---------------------------------------------------------------------------
__global__ void __launch_bounds__(256) gemm_kernel(const float* __restrict__ x, int n) {
    __shared__ float xs[128][DM];  // 32KB
    __shared__ float gs[DM][64];   // 16KB

    const int tid = threadIdx.x;
    const int rowBase = blockIdx.x * 128;
    const int colBase = blockIdx.y * 64;

    // load G half: 64 rows x 16 float4
    for (int i = tid; i < 64 * 16; i += 256) {
        int d = i >> 4, q = i & 15;
        ((float4*)&gs[d][0])[q] = *(const float4*)&g_G[d * NC + colBase + q * 4];
    }
    // load x tile: 128 rows x 16 float4 (zero-fill OOB)
    {
        const float4* x4 = (const float4*)x;
        for (int i = tid; i < 128 * 16; i += 256) {
            int r = i >> 4, q = i & 15;
            int gr = rowBase + r;
            float4 v = make_float4(0.f, 0.f, 0.f, 0.f);
            if (gr < n) v = x4[gr * 16 + q];
            ((float4*)&xs[r][0])[q] = v;
        }
    }
    __syncthreads();

    const int tcol = tid & 15;   // 16 col-groups of 4
    const int trow = tid >> 4;   // 16 row-groups of 8
    const int r0 = trow * 8;
    const int c0 = tcol * 4;

    float acc[8][4] = {};
#pragma unroll 16
    for (int d = 0; d < 64; d++) {
        float4 g = *(const float4*)&gs[d][c0];
#pragma unroll
        for (int r = 0; r < 8; r++) {
            float xv = xs[r0 + r][d];  // 2 distinct addrs per warp -> broadcast
            acc[r][0] += xv * g.x;
            acc[r][1] += xv * g.y;
            acc[r][2] += xv * g.z;
            acc[r][3] += xv * g.w;
        }
    }
#pragma unroll
    for (int r = 0; r < 8; r++) {
        int gr = rowBase + r0 + r;
        if (gr < n)
            *(float4*)&g_Z[gr * NC + colBase + c0] =
                make_float4(acc[r][0], acc[r][1], acc[r][2], acc[r][3]);
    }
}

// ---------------------------------------------------------------------------
// Attention: warp per node. Lane layout: group g = lane>>2 handles neighbor g,
// sub-lane t = lane&3 handles dims [16t, 16t+16).
// s_h[j] = 8 * ( (y_h[i] + v_h) . x[col_j] )   (node-constant terms cancel
// in softmax). out[i*8+j] = 0.5*(softmax_h0[j] + softmax_h1[j]).
// ---------------------------------------------------------------------------
__device__ __forceinline__ float dot4(float4 a, float4 b) {
    return a.x * b.x + a.y * b.y + a.z * b.z + a.w * b.w;
}

__global__ void __launch_bounds__(256) attn_kernel(const float* __restrict__ x,
                                                   const int* __restrict__ ei,
                                                   float* __restrict__ out,
                                                   int n, int E) {
    __shared__ float wsh[8][NC];  // w = y + v, one row per warp (node)
    const int tid = threadIdx.x;
    const int lane = tid & 31;
    const int w = tid >> 5;
    const int node = blockIdx.x * 8 + w;
    const int* cols = ei + E;  // edge_index[1]

    if (node < n) {
        float4 y = *(const float4*)&g_Z[node * NC + lane * 4];
        float4 vv = *(const float4*)&g_v[lane * 4];
        *(float4*)&wsh[w][lane * 4] =
            make_float4(y.x + vv.x, y.y + vv.y, y.z + vv.z, y.w + vv.w);
    }
    __syncwarp();
    if (node >= n) return;

    const int g = lane >> 2;
    const int t = lane & 3;
    const int c = cols[node * DEG + g];

    float4 w00 = *(const float4*)&wsh[w][16 * t + 0];
    float4 w01 = *(const float4*)&wsh[w][16 * t + 4];
    float4 w02 = *(const float4*)&wsh[w][16 * t + 8];
    float4 w03 = *(const float4*)&wsh[w][16 * t + 12];
    float4 w10 = *(const float4*)&wsh[w][64 + 16 * t + 0];
    float4 w11 = *(const float4*)&wsh[w][64 + 16 * t + 4];
    float4 w12 = *(const float4*)&wsh[w][64 + 16 * t + 8];
    float4 w13 = *(const float4*)&wsh[w][64 + 16 * t + 12];

    const float4* xc4 = (const float4*)(x + (size_t)c * DM + 16 * t);
    float4 xa = xc4[0], xb = xc4[1], xcv = xc4[2], xd = xc4[3];

    float p0 = dot4(w00, xa) + dot4(w01, xb) + dot4(w02, xcv) + dot4(w03, xd);
    float p1 = dot4(w10, xa) + dot4(w11, xb) + dot4(w12, xcv) + dot4(w13, xd);

    // reduce within 4-lane group
    p0 += __shfl_xor_sync(FULL, p0, 1);
    p0 += __shfl_xor_sync(FULL, p0, 2);
    p1 += __shfl_xor_sync(FULL, p1, 1);
    p1 += __shfl_xor_sync(FULL, p1, 2);

    float s0 = p0 * 8.0f;  // reference divides by scale = 1/sqrt(64)
    float s1 = p1 * 8.0f;

    // cross-group max (8 groups; xor 4,8,16 stays within warp)
    float m0 = s0, m1 = s1;
    m0 = fmaxf(m0, __shfl_xor_sync(FULL, m0, 4));
    m0 = fmaxf(m0, __shfl_xor_sync(FULL, m0, 8));
    m0 = fmaxf(m0, __shfl_xor_sync(FULL, m0, 16));
    m1 = fmaxf(m1, __shfl_xor_sync(FULL, m1, 4));
    m1 = fmaxf(m1, __shfl_xor_sync(FULL, m1, 8));
    m1 = fmaxf(m1, __shfl_xor_sync(FULL, m1, 16));

    float e0 = __expf(s0 - m0);
    float e1 = __expf(s1 - m1);

    float z0 = e0, z1 = e1;
    z0 += __shfl_xor_sync(FULL, z0, 4);
    z0 += __shfl_xor_sync(FULL, z0, 8);
    z0 += __shfl_xor_sync(FULL, z0, 16);
    z1 += __shfl_xor_sync(FULL, z1, 4);
    z1 += __shfl_xor_sync(FULL, z1, 8);
    z1 += __shfl_xor_sync(FULL, z1, 16);

    if (t == 0) out[node * DEG + g] = 0.5f * (e0 / z0 + e1 / z1);
}

// ---------------------------------------------------------------------------
extern "C" void kernel_launch(void* const* d_in, const int* in_sizes, int n_in,
                              void* d_out, int out_size) {
    const float* x = (const float*)d_in[0];
    const float* W = (const float*)d_in[1];
    const float* b = (const float*)d_in[2];
    const int* ei = (const int*)d_in[3];
    float* out = (float*)d_out;

    const int n = in_sizes[0] / DM;   // 100000
    const int E = in_sizes[3] / 2;    // 800000

    prologue_kernel<<<2, 256>>>(W, b);

    dim3 ggrid((n + 127) / 128, 2);
    gemm_kernel<<<ggrid, 256>>>(x, n);

    attn_kernel<<<(n + 7) / 8, 256>>>(x, ei, out, n, E);
}

// round 4
// speedup vs baseline: 1.2183x; 1.2183x over previous
#include <cuda_runtime.h>
#include <cuda_bf16.h>
#include <cstdint>

#define FULL 0xFFFFFFFFu

constexpr int DM   = 64;     // model dim (K)
constexpr int NC   = 128;    // 2 heads * 64 (N)
constexpr int DEG  = 8;
constexpr int TILE = 128;    // nodes per CTA (M tile)

// ---------------- device scratch (no runtime allocation) -------------------
__device__ __align__(16) __nv_bfloat16 g_GT_hi[NC * DM];  // GT[n][k] = G[k][n]
__device__ __align__(16) __nv_bfloat16 g_GT_lo[NC * DM];
__device__ float g_v[NC];

// ---------------- smem layout (dynamic, bytes from base) --------------------
// bf16 tiles: 128 rows x 64 cols, row stride 144B (72 bf16) -> conflict-free
// ldmatrix (row r chunk base banks stride by 16B per row).
constexpr int STRB  = 144;
constexpr int TBYTES = 128 * STRB;           // 18432
constexpr int SM_V   = 0;                    // 128 floats (512B)
constexpr int SM_AHI = 1024;
constexpr int SM_ALO = SM_AHI + TBYTES;      // 19456
constexpr int SM_BHI = SM_ALO + TBYTES;      // 37888
constexpr int SM_BLO = SM_BHI + TBYTES;      // 56320
constexpr int SMEM_BYTES = SM_BLO + TBYTES;  // 74752
// w staging reuses the A/B region after MMA completes:
constexpr int SM_WSH   = 1024;
constexpr int WSTRIDE  = 132;                // floats per w row (16B-aligned stride)

// ---------------- ptx helpers ------------------------------------------------
__device__ __forceinline__ uint32_t smem_u32(const void* p) {
    uint32_t a;
    asm("{ .reg .u64 t; cvta.to.shared.u64 t, %1; cvt.u32.u64 %0, t; }" : "=r"(a) : "l"(p));
    return a;
}
__device__ __forceinline__ void ldsm_x4(uint32_t* r, uint32_t addr) {
    asm volatile("ldmatrix.sync.aligned.m8n8.x4.shared.b16 {%0,%1,%2,%3}, [%4];"
                 : "=r"(r[0]), "=r"(r[1]), "=r"(r[2]), "=r"(r[3]) : "r"(addr));
}
__device__ __forceinline__ void mma16816(float* c, const uint32_t* a, uint32_t b0, uint32_t b1) {
    asm volatile(
        "mma.sync.aligned.m16n8k16.row.col.f32.bf16.bf16.f32 "
        "{%0,%1,%2,%3}, {%4,%5,%6,%7}, {%8,%9}, {%0,%1,%2,%3};"
        : "+f"(c[0]), "+f"(c[1]), "+f"(c[2]), "+f"(c[3])
        : "r"(a[0]), "r"(a[1]), "r"(a[2]), "r"(a[3]), "r"(b0), "r"(b1));
}

// bf16 split helpers
__device__ __forceinline__ uint32_t split2(float a, float b, float& la, float& lb) {
    __nv_bfloat16 ha = __float2bfloat16(a), hb = __float2bfloat16(b);
    la = a - __bfloat162float(ha);
    lb = b - __bfloat162float(hb);
    __nv_bfloat162 p = __halves2bfloat162(ha, hb);
    return *reinterpret_cast<uint32_t*>(&p);
}
__device__ __forceinline__ uint32_t pack2(float a, float b) {
    __nv_bfloat162 p = __floats2bfloat162_rn(a, b);
    return *reinterpret_cast<uint32_t*>(&p);
}

// ---------------------------------------------------------------------------
// Prologue: M_h = A_h^T B_h, emitted transposed as bf16 hi/lo:
//   GT[(h*64+e)][d] = M_h[d][e];  v[h*64+e] = sum_t B_h[t][e]*b[h*192+t].
// ---------------------------------------------------------------------------
__global__ void __launch_bounds__(256) prologue_kernel(const float* __restrict__ W,
                                                       const float* __restrict__ b) {
    const int h  = blockIdx.x >> 3;
    const int d0 = (blockIdx.x & 7) * 8;
    __shared__ float Bs[64][64];
    __shared__ float As[64][8];
    const int tid = threadIdx.x;

    const float4* Wk = (const float4*)(W + (h * 192 + 64) * 64);
    float4* Bs4 = (float4*)Bs;
    for (int i = tid; i < 1024; i += 256) Bs4[i] = Wk[i];
    const float* Wq = W + (h * 192) * 64;
    if (tid < 128) {
        int t = tid >> 1, j = (tid & 1) * 4;
        *(float4*)&As[t][j] = *(const float4*)&Wq[t * 64 + d0 + j];
    }
    __syncthreads();

    const int e  = tid & 63;
    const int dj = tid >> 6;  // 0..3
    float a0 = 0.f, a1 = 0.f;
#pragma unroll 8
    for (int t = 0; t < 64; t++) {
        float bv = Bs[t][e];
        a0 += As[t][dj] * bv;
        a1 += As[t][dj + 4] * bv;
    }
    const int row = h * 64 + e;
    {
        __nv_bfloat16 hi = __float2bfloat16(a0);
        g_GT_hi[row * 64 + d0 + dj] = hi;
        g_GT_lo[row * 64 + d0 + dj] = __float2bfloat16(a0 - __bfloat162float(hi));
    }
    {
        __nv_bfloat16 hi = __float2bfloat16(a1);
        g_GT_hi[row * 64 + d0 + dj + 4] = hi;
        g_GT_lo[row * 64 + d0 + dj + 4] = __float2bfloat16(a1 - __bfloat162float(hi));
    }
    if (d0 == 0 && dj == 0) {
        float s = 0.f;
#pragma unroll 8
        for (int t = 0; t < 64; t++) s += Bs[t][e] * b[h * 192 + t];
        g_v[row] = s;
    }
}

// ---------------------------------------------------------------------------
// Fused kernel: per CTA of 128 nodes
//   1) x tile -> bf16 hi/lo smem; GT hi/lo -> smem; v -> smem
//   2) mma.sync bf16 (3-term split): w_raw[128][128] in registers (fragment)
//   3) epilogue: +v, stage into smem w
//   4) attention: warp per 16 nodes, 4 lanes/neighbor, edge softmax
// ---------------------------------------------------------------------------
__device__ __forceinline__ float dot4(float4 a, float4 b) {
    return a.x * b.x + a.y * b.y + a.z * b.z + a.w * b.w;
}

__global__ void __launch_bounds__(256) fused_kernel(const float* __restrict__ x,
                                                    const int* __restrict__ ei,
                                                    float* __restrict__ out,
                                                    int n, int E) {
    extern __shared__ char smem[];
    const uint32_t sb = smem_u32(smem);
    const int tid  = threadIdx.x;
    const int lane = tid & 31;
    const int wid  = tid >> 5;
    const int rowBase = blockIdx.x * TILE;

    float* vsh = (float*)(smem + SM_V);

    // ---- load B = GT hi/lo into strided smem (16B chunks) ----
    {
        const uint4* gth = (const uint4*)g_GT_hi;
        const uint4* gtl = (const uint4*)g_GT_lo;
        for (int i = tid; i < 1024; i += 256) {
            int r = i >> 3, c = i & 7;
            int off = r * STRB + c * 16;
            *(uint4*)(smem + SM_BHI + off) = gth[i];
            *(uint4*)(smem + SM_BLO + off) = gtl[i];
        }
    }
    // ---- convert x tile into bf16 hi/lo ----
    {
        const float4* x4 = (const float4*)x;
        for (int i = tid; i < 1024; i += 256) {
            int r = i >> 3, c = i & 7;
            int gr = rowBase + r;
            float4 f0 = make_float4(0.f, 0.f, 0.f, 0.f), f1 = f0;
            if (gr < n) { f0 = x4[gr * 16 + c * 2]; f1 = x4[gr * 16 + c * 2 + 1]; }
            float l0, l1, l2, l3, l4, l5, l6, l7;
            uint4 hi, lo;
            hi.x = split2(f0.x, f0.y, l0, l1);
            hi.y = split2(f0.z, f0.w, l2, l3);
            hi.z = split2(f1.x, f1.y, l4, l5);
            hi.w = split2(f1.z, f1.w, l6, l7);
            lo.x = pack2(l0, l1); lo.y = pack2(l2, l3);
            lo.z = pack2(l4, l5); lo.w = pack2(l6, l7);
            int off = r * STRB + c * 16;
            *(uint4*)(smem + SM_AHI + off) = hi;
            *(uint4*)(smem + SM_ALO + off) = lo;
        }
    }
    if (tid < NC) vsh[tid] = g_v[tid];
    __syncthreads();

    // ---- MMA: warp computes rows [wid*16, wid*16+16) x 128 cols ----
    const int r0 = wid * 16;
    float acc[16][4];
#pragma unroll
    for (int c = 0; c < 16; c++) { acc[c][0] = acc[c][1] = acc[c][2] = acc[c][3] = 0.f; }

    const uint32_t aRowOff = (uint32_t)((r0 + (lane & 15)) * STRB + ((lane >> 4) << 4));
    const uint32_t bRowOff = (uint32_t)(((lane & 7) + ((lane >> 4) << 3)) * STRB + (((lane >> 3) & 1) << 4));

#pragma unroll
    for (int s = 0; s < 3; s++) {
        const uint32_t Abase = sb + (s == 2 ? SM_ALO : SM_AHI) + aRowOff;
        const uint32_t Bbase = sb + (s == 1 ? SM_BLO : SM_BHI) + bRowOff;
#pragma unroll
        for (int k = 0; k < 4; k++) {
            uint32_t a[4];
            ldsm_x4(a, Abase + k * 32);
#pragma unroll
            for (int nc = 0; nc < 8; nc++) {
                uint32_t b[4];
                ldsm_x4(b, Bbase + nc * 16 * STRB + k * 32);
                mma16816(acc[2 * nc], a, b[0], b[1]);
                mma16816(acc[2 * nc + 1], a, b[2], b[3]);
            }
        }
    }

    __syncthreads();  // all MMA smem reads done; safe to reuse region for w

    // ---- epilogue: w = D + v into smem ----
    float* wsh = (float*)(smem + SM_WSH);
    {
        const int g = lane >> 2, tig = lane & 3;
        const int row0 = r0 + g, row1 = r0 + 8 + g;
#pragma unroll
        for (int c = 0; c < 16; c++) {
            const int col = 8 * c + 2 * tig;
            float v0 = vsh[col], v1 = vsh[col + 1];
            *(float2*)&wsh[row0 * WSTRIDE + col] = make_float2(acc[c][0] + v0, acc[c][1] + v1);
            *(float2*)&wsh[row1 * WSTRIDE + col] = make_float2(acc[c][2] + v0, acc[c][3] + v1);
        }
    }
    __syncwarp();

    // ---- attention: warp handles its own 16 rows; 4 lanes per neighbor ----
    const int* cols = ei + E;
    const int g = lane >> 2;
    const int t = lane & 3;
#pragma unroll 1
    for (int it = 0; it < 16; it++) {
        const int r = r0 + it;
        const int node = rowBase + r;
        if (node >= n) break;

        const int c = cols[node * DEG + g];
        const float* wrow = wsh + r * WSTRIDE;

        float4 w00 = *(const float4*)(wrow + 16 * t + 0);
        float4 w01 = *(const float4*)(wrow + 16 * t + 4);
        float4 w02 = *(const float4*)(wrow + 16 * t + 8);
        float4 w03 = *(const float4*)(wrow + 16 * t + 12);
        float4 w10 = *(const float4*)(wrow + 64 + 16 * t + 0);
        float4 w11 = *(const float4*)(wrow + 64 + 16 * t + 4);
        float4 w12 = *(const float4*)(wrow + 64 + 16 * t + 8);
        float4 w13 = *(const float4*)(wrow + 64 + 16 * t + 12);

        const float4* xc4 = (const float4*)(x + (size_t)c * DM + 16 * t);
        float4 xa = xc4[0], xb = xc4[1], xc = xc4[2], xd = xc4[3];

        float p0 = dot4(w00, xa) + dot4(w01, xb) + dot4(w02, xc) + dot4(w03, xd);
        float p1 = dot4(w10, xa) + dot4(w11, xb) + dot4(w12, xc) + dot4(w13, xd);

        p0 += __shfl_xor_sync(FULL, p0, 1);
        p0 += __shfl_xor_sync(FULL, p0, 2);
        p1 += __shfl_xor_sync(FULL, p1, 1);
        p1 += __shfl_xor_sync(FULL, p1, 2);

        float s0 = p0 * 8.0f;
        float s1 = p1 * 8.0f;

        float m0 = s0, m1 = s1;
        m0 = fmaxf(m0, __shfl_xor_sync(FULL, m0, 4));
        m0 = fmaxf(m0, __shfl_xor_sync(FULL, m0, 8));
        m0 = fmaxf(m0, __shfl_xor_sync(FULL, m0, 16));
        m1 = fmaxf(m1, __shfl_xor_sync(FULL, m1, 4));
        m1 = fmaxf(m1, __shfl_xor_sync(FULL, m1, 8));
        m1 = fmaxf(m1, __shfl_xor_sync(FULL, m1, 16));

        float e0 = __expf(s0 - m0);
        float e1 = __expf(s1 - m1);

        float z0 = e0, z1 = e1;
        z0 += __shfl_xor_sync(FULL, z0, 4);
        z0 += __shfl_xor_sync(FULL, z0, 8);
        z0 += __shfl_xor_sync(FULL, z0, 16);
        z1 += __shfl_xor_sync(FULL, z1, 4);
        z1 += __shfl_xor_sync(FULL, z1, 8);
        z1 += __shfl_xor_sync(FULL, z1, 16);

        if (t == 0) out[node * DEG + g] = 0.5f * (e0 / z0 + e1 / z1);
    }
}

// ---------------------------------------------------------------------------
extern "C" void kernel_launch(void* const* d_in, const int* in_sizes, int n_in,
                              void* d_out, int out_size) {
    const float* x = (const float*)d_in[0];
    const float* W = (const float*)d_in[1];
    const float* b = (const float*)d_in[2];
    const int* ei  = (const int*)d_in[3];
    float* out = (float*)d_out;

    const int n = in_sizes[0] / DM;
    const int E = in_sizes[3] / 2;

    static bool attr_set = false;
    if (!attr_set) {
        cudaFuncSetAttribute(fused_kernel, cudaFuncAttributeMaxDynamicSharedMemorySize, SMEM_BYTES);
        attr_set = true;
    }

    prologue_kernel<<<16, 256>>>(W, b);
    fused_kernel<<<(n + TILE - 1) / TILE, 256, SMEM_BYTES>>>(x, ei, out, n, E);
}

// round 5
// speedup vs baseline: 1.3730x; 1.1270x over previous
#include <cuda_runtime.h>
#include <cuda_bf16.h>
#include <cstdint>

#define FULL 0xFFFFFFFFu

constexpr int DM   = 64;     // model dim (K)
constexpr int NC   = 128;    // 2 heads * 64 (N)
constexpr int DEG  = 8;
constexpr int TILE = 128;    // nodes per CTA (M tile)

// ---------------- device scratch (no runtime allocation) -------------------
__device__ __align__(16) __nv_bfloat16 g_GT_hi[NC * DM];  // GT[n][k] = G[k][n]
__device__ __align__(16) __nv_bfloat16 g_GT_lo[NC * DM];
__device__ float g_v[NC];

// ---------------- smem layout (dynamic, bytes from base) --------------------
// bf16 tiles: 128 rows x 64 cols, row stride 144B -> conflict-free ldmatrix.
constexpr int STRB   = 144;
constexpr int TBYTES = 128 * STRB;           // 18432
constexpr int SM_V   = 0;                    // 128 floats
constexpr int SM_AHI = 1024;
constexpr int SM_ALO = SM_AHI + TBYTES;      // 19456
constexpr int SM_BHI = SM_ALO + TBYTES;      // 37888
constexpr int SM_BLO = SM_BHI + TBYTES;      // 56320  (A/B end 74752)
// w staging reuses the A/B region after MMA completes:
constexpr int SM_WSH   = 1024;
constexpr int WSTRIDE  = 132;                // floats per w row
constexpr int SM_SC    = SM_WSH + TILE * WSTRIDE * 4;  // 68608 (scores)
constexpr int SC_STR   = 20;                 // floats per score row (16B-mult)
constexpr int SMEM_BYTES = SM_SC + TILE * SC_STR * 4;  // 78848

// ---------------- ptx helpers ------------------------------------------------
__device__ __forceinline__ uint32_t smem_u32(const void* p) {
    uint32_t a;
    asm("{ .reg .u64 t; cvta.to.shared.u64 t, %1; cvt.u32.u64 %0, t; }" : "=r"(a) : "l"(p));
    return a;
}
__device__ __forceinline__ void ldsm_x4(uint32_t* r, uint32_t addr) {
    asm volatile("ldmatrix.sync.aligned.m8n8.x4.shared.b16 {%0,%1,%2,%3}, [%4];"
                 : "=r"(r[0]), "=r"(r[1]), "=r"(r[2]), "=r"(r[3]) : "r"(addr));
}
__device__ __forceinline__ void mma16816(float* c, const uint32_t* a, uint32_t b0, uint32_t b1) {
    asm volatile(
        "mma.sync.aligned.m16n8k16.row.col.f32.bf16.bf16.f32 "
        "{%0,%1,%2,%3}, {%4,%5,%6,%7}, {%8,%9}, {%0,%1,%2,%3};"
        : "+f"(c[0]), "+f"(c[1]), "+f"(c[2]), "+f"(c[3])
        : "r"(a[0]), "r"(a[1]), "r"(a[2]), "r"(a[3]), "r"(b0), "r"(b1));
}

// bf16 split helpers
__device__ __forceinline__ uint32_t split2(float a, float b, float& la, float& lb) {
    __nv_bfloat16 ha = __float2bfloat16(a), hb = __float2bfloat16(b);
    la = a - __bfloat162float(ha);
    lb = b - __bfloat162float(hb);
    __nv_bfloat162 p = __halves2bfloat162(ha, hb);
    return *reinterpret_cast<uint32_t*>(&p);
}
__device__ __forceinline__ uint32_t pack2(float a, float b) {
    __nv_bfloat162 p = __floats2bfloat162_rn(a, b);
    return *reinterpret_cast<uint32_t*>(&p);
}

// ---------------------------------------------------------------------------
// Prologue: M_h = A_h^T B_h, emitted transposed as bf16 hi/lo:
//   GT[(h*64+e)][d] = M_h[d][e];  v[h*64+e] = sum_t B_h[t][e]*b[h*192+t].
// ---------------------------------------------------------------------------
__global__ void __launch_bounds__(256) prologue_kernel(const float* __restrict__ W,
                                                       const float* __restrict__ b) {
    const int h  = blockIdx.x >> 3;
    const int d0 = (blockIdx.x & 7) * 8;
    __shared__ float Bs[64][64];
    __shared__ float As[64][8];
    const int tid = threadIdx.x;

    const float4* Wk = (const float4*)(W + (h * 192 + 64) * 64);
    float4* Bs4 = (float4*)Bs;
    for (int i = tid; i < 1024; i += 256) Bs4[i] = Wk[i];
    const float* Wq = W + (h * 192) * 64;
    if (tid < 128) {
        int t = tid >> 1, j = (tid & 1) * 4;
        *(float4*)&As[t][j] = *(const float4*)&Wq[t * 64 + d0 + j];
    }
    __syncthreads();

    const int e  = tid & 63;
    const int dj = tid >> 6;  // 0..3
    float a0 = 0.f, a1 = 0.f;
#pragma unroll 8
    for (int t = 0; t < 64; t++) {
        float bv = Bs[t][e];
        a0 += As[t][dj] * bv;
        a1 += As[t][dj + 4] * bv;
    }
    const int row = h * 64 + e;
    {
        __nv_bfloat16 hi = __float2bfloat16(a0);
        g_GT_hi[row * 64 + d0 + dj] = hi;
        g_GT_lo[row * 64 + d0 + dj] = __float2bfloat16(a0 - __bfloat162float(hi));
    }
    {
        __nv_bfloat16 hi = __float2bfloat16(a1);
        g_GT_hi[row * 64 + d0 + dj + 4] = hi;
        g_GT_lo[row * 64 + d0 + dj + 4] = __float2bfloat16(a1 - __bfloat162float(hi));
    }
    if (d0 == 0 && dj == 0) {
        float s = 0.f;
#pragma unroll 8
        for (int t = 0; t < 64; t++) s += Bs[t][e] * b[h * 192 + t];
        g_v[row] = s;
    }
}

// ---------------------------------------------------------------------------
// Fused kernel
// ---------------------------------------------------------------------------
__device__ __forceinline__ float dot4(float4 a, float4 b) {
    return a.x * b.x + a.y * b.y + a.z * b.z + a.w * b.w;
}

__global__ void __launch_bounds__(256) fused_kernel(const float* __restrict__ x,
                                                    const int* __restrict__ ei,
                                                    float* __restrict__ out,
                                                    int n, int E) {
    extern __shared__ char smem[];
    const uint32_t sb = smem_u32(smem);
    const int tid  = threadIdx.x;
    const int lane = tid & 31;
    const int wid  = tid >> 5;
    const int rowBase = blockIdx.x * TILE;

    float* vsh = (float*)(smem + SM_V);

    // ---- load B = GT hi/lo ----
    {
        const uint4* gth = (const uint4*)g_GT_hi;
        const uint4* gtl = (const uint4*)g_GT_lo;
        for (int i = tid; i < 1024; i += 256) {
            int r = i >> 3, c = i & 7;
            int off = r * STRB + c * 16;
            *(uint4*)(smem + SM_BHI + off) = gth[i];
            *(uint4*)(smem + SM_BLO + off) = gtl[i];
        }
    }
    // ---- convert x tile into bf16 hi/lo ----
    {
        const float4* x4 = (const float4*)x;
        for (int i = tid; i < 1024; i += 256) {
            int r = i >> 3, c = i & 7;
            int gr = rowBase + r;
            float4 f0 = make_float4(0.f, 0.f, 0.f, 0.f), f1 = f0;
            if (gr < n) { f0 = x4[gr * 16 + c * 2]; f1 = x4[gr * 16 + c * 2 + 1]; }
            float l0, l1, l2, l3, l4, l5, l6, l7;
            uint4 hi, lo;
            hi.x = split2(f0.x, f0.y, l0, l1);
            hi.y = split2(f0.z, f0.w, l2, l3);
            hi.z = split2(f1.x, f1.y, l4, l5);
            hi.w = split2(f1.z, f1.w, l6, l7);
            lo.x = pack2(l0, l1); lo.y = pack2(l2, l3);
            lo.z = pack2(l4, l5); lo.w = pack2(l6, l7);
            int off = r * STRB + c * 16;
            *(uint4*)(smem + SM_AHI + off) = hi;
            *(uint4*)(smem + SM_ALO + off) = lo;
        }
    }
    if (tid < NC) vsh[tid] = g_v[tid];
    __syncthreads();

    // ---- MMA: 2-D warp partition: wr=wid>>1 (rows wr*32..+32), wc=wid&1
    //      (cols wc*64..+64). Split-term reuse: per k load a_hi/a_lo for both
    //      16-row blocks once; per 16-col block load b_hi (used by ahi+alo)
    //      then b_lo (used by ahi). ----
    const int wr = wid >> 1;
    const int wc = wid & 1;
    float acc[16][4];  // [rb*8 + nb*2 + j][4]
#pragma unroll
    for (int f = 0; f < 16; f++) { acc[f][0] = acc[f][1] = acc[f][2] = acc[f][3] = 0.f; }

    const uint32_t aOff0 = (uint32_t)((wr * 32 + (lane & 15)) * STRB + ((lane >> 4) << 4));
    const uint32_t aOff1 = aOff0 + 16 * STRB;
    const uint32_t bOffL =
        (uint32_t)(((lane & 7) + ((lane >> 4) << 3)) * STRB + (((lane >> 3) & 1) << 4));

#pragma unroll
    for (int k = 0; k < 4; k++) {
        uint32_t ah0[4], ah1[4], al0[4], al1[4];
        ldsm_x4(ah0, sb + SM_AHI + aOff0 + k * 32);
        ldsm_x4(ah1, sb + SM_AHI + aOff1 + k * 32);
        ldsm_x4(al0, sb + SM_ALO + aOff0 + k * 32);
        ldsm_x4(al1, sb + SM_ALO + aOff1 + k * 32);
#pragma unroll
        for (int nb = 0; nb < 4; nb++) {
            const uint32_t bRow = (uint32_t)((wc * 64 + nb * 16) * STRB) + bOffL + k * 32;
            uint32_t bh[4], bl[4];
            ldsm_x4(bh, sb + SM_BHI + bRow);
            mma16816(acc[nb * 2 + 0], ah0, bh[0], bh[1]);
            mma16816(acc[nb * 2 + 1], ah0, bh[2], bh[3]);
            mma16816(acc[8 + nb * 2 + 0], ah1, bh[0], bh[1]);
            mma16816(acc[8 + nb * 2 + 1], ah1, bh[2], bh[3]);
            mma16816(acc[nb * 2 + 0], al0, bh[0], bh[1]);
            mma16816(acc[nb * 2 + 1], al0, bh[2], bh[3]);
            mma16816(acc[8 + nb * 2 + 0], al1, bh[0], bh[1]);
            mma16816(acc[8 + nb * 2 + 1], al1, bh[2], bh[3]);
            ldsm_x4(bl, sb + SM_BLO + bRow);
            mma16816(acc[nb * 2 + 0], ah0, bl[0], bl[1]);
            mma16816(acc[nb * 2 + 1], ah0, bl[2], bl[3]);
            mma16816(acc[8 + nb * 2 + 0], ah1, bl[0], bl[1]);
            mma16816(acc[8 + nb * 2 + 1], ah1, bl[2], bl[3]);
        }
    }

    __syncthreads();  // all MMA smem reads done; safe to overlay w

    // ---- epilogue: w = D + v into smem ----
    float* wsh = (float*)(smem + SM_WSH);
    {
        const int g = lane >> 2, tig = lane & 3;
#pragma unroll
        for (int rb = 0; rb < 2; rb++) {
            const int row0 = wr * 32 + rb * 16 + g;
#pragma unroll
            for (int nb = 0; nb < 4; nb++) {
#pragma unroll
                for (int j = 0; j < 2; j++) {
                    const int col = wc * 64 + nb * 16 + j * 8 + 2 * tig;
                    const float* a = acc[rb * 8 + nb * 2 + j];
                    float v0 = vsh[col], v1 = vsh[col + 1];
                    *(float2*)&wsh[row0 * WSTRIDE + col] = make_float2(a[0] + v0, a[1] + v1);
                    *(float2*)&wsh[(row0 + 8) * WSTRIDE + col] = make_float2(a[2] + v0, a[3] + v1);
                }
            }
        }
    }
    __syncthreads();  // w fully written (rows span warps)

    // ---- score phase: warp -> 16 nodes; 4 lanes per neighbor; prefetched
    //      gather; only the 4 dot-reduce shuffles; scores to smem ----
    float* sc = (float*)(smem + SM_SC);
    const int* cols = ei + E;
    const int r0 = wid * 16;
    const int g = lane >> 2;
    const int t = lane & 3;
    const int nWarp = min(16, n - (rowBase + r0));  // nodes this warp owns

    if (nWarp > 0) {
        const int* colp = cols + (size_t)(rowBase + r0) * DEG + g;
        int c = colp[0];
        const float4* xp = (const float4*)(x + (size_t)c * DM + 16 * t);
        float4 xa = xp[0], xb = xp[1], xc2 = xp[2], xd = xp[3];

#pragma unroll 1
        for (int it = 0; it < nWarp; it++) {
            float4 cxa = xa, cxb = xb, cxc = xc2, cxd = xd;
            if (it + 1 < nWarp) {  // prefetch next node's row
                int cn = colp[(it + 1) * DEG];
                const float4* xn = (const float4*)(x + (size_t)cn * DM + 16 * t);
                xa = xn[0]; xb = xn[1]; xc2 = xn[2]; xd = xn[3];
            }
            const int r = r0 + it;
            const float* wrow = wsh + r * WSTRIDE;
            float4 w00 = *(const float4*)(wrow + 16 * t + 0);
            float4 w01 = *(const float4*)(wrow + 16 * t + 4);
            float4 w02 = *(const float4*)(wrow + 16 * t + 8);
            float4 w03 = *(const float4*)(wrow + 16 * t + 12);
            float4 w10 = *(const float4*)(wrow + 64 + 16 * t + 0);
            float4 w11 = *(const float4*)(wrow + 64 + 16 * t + 4);
            float4 w12 = *(const float4*)(wrow + 64 + 16 * t + 8);
            float4 w13 = *(const float4*)(wrow + 64 + 16 * t + 12);

            float p0 = dot4(w00, cxa) + dot4(w01, cxb) + dot4(w02, cxc) + dot4(w03, cxd);
            float p1 = dot4(w10, cxa) + dot4(w11, cxb) + dot4(w12, cxc) + dot4(w13, cxd);

            p0 += __shfl_xor_sync(FULL, p0, 1);
            p0 += __shfl_xor_sync(FULL, p0, 2);
            p1 += __shfl_xor_sync(FULL, p1, 1);
            p1 += __shfl_xor_sync(FULL, p1, 2);

            if (t == 0) {
                sc[r * SC_STR + g] = p0 * 8.0f;
                sc[r * SC_STR + 8 + g] = p1 * 8.0f;
            }
        }
    }
    __syncwarp();

    // ---- softmax phase: lane = node (lanes 0..15), zero shuffles ----
    if (lane < nWarp) {
        const int r = r0 + lane;
        const int node = rowBase + r;
        const float* srow = sc + r * SC_STR;
        float4 sa = *(const float4*)(srow + 0);
        float4 sb4 = *(const float4*)(srow + 4);
        float4 ta = *(const float4*)(srow + 8);
        float4 tb = *(const float4*)(srow + 12);

        float m0 = fmaxf(fmaxf(fmaxf(sa.x, sa.y), fmaxf(sa.z, sa.w)),
                         fmaxf(fmaxf(sb4.x, sb4.y), fmaxf(sb4.z, sb4.w)));
        float m1 = fmaxf(fmaxf(fmaxf(ta.x, ta.y), fmaxf(ta.z, ta.w)),
                         fmaxf(fmaxf(tb.x, tb.y), fmaxf(tb.z, tb.w)));

        float e0[8], e1[8];
        e0[0] = __expf(sa.x - m0); e0[1] = __expf(sa.y - m0);
        e0[2] = __expf(sa.z - m0); e0[3] = __expf(sa.w - m0);
        e0[4] = __expf(sb4.x - m0); e0[5] = __expf(sb4.y - m0);
        e0[6] = __expf(sb4.z - m0); e0[7] = __expf(sb4.w - m0);
        e1[0] = __expf(ta.x - m1); e1[1] = __expf(ta.y - m1);
        e1[2] = __expf(ta.z - m1); e1[3] = __expf(ta.w - m1);
        e1[4] = __expf(tb.x - m1); e1[5] = __expf(tb.y - m1);
        e1[6] = __expf(tb.z - m1); e1[7] = __expf(tb.w - m1);

        float z0 = (e0[0] + e0[1]) + (e0[2] + e0[3]) + (e0[4] + e0[5]) + (e0[6] + e0[7]);
        float z1 = (e1[0] + e1[1]) + (e1[2] + e1[3]) + (e1[4] + e1[5]) + (e1[6] + e1[7]);
        float i0 = 0.5f / z0, i1 = 0.5f / z1;

        float4 o0 = make_float4(e0[0] * i0 + e1[0] * i1, e0[1] * i0 + e1[1] * i1,
                                e0[2] * i0 + e1[2] * i1, e0[3] * i0 + e1[3] * i1);
        float4 o1 = make_float4(e0[4] * i0 + e1[4] * i1, e0[5] * i0 + e1[5] * i1,
                                e0[6] * i0 + e1[6] * i1, e0[7] * i0 + e1[7] * i1);
        float4* op = (float4*)(out + (size_t)node * DEG);
        op[0] = o0;
        op[1] = o1;
    }
}

// ---------------------------------------------------------------------------
extern "C" void kernel_launch(void* const* d_in, const int* in_sizes, int n_in,
                              void* d_out, int out_size) {
    const float* x = (const float*)d_in[0];
    const float* W = (const float*)d_in[1];
    const float* b = (const float*)d_in[2];
    const int* ei  = (const int*)d_in[3];
    float* out = (float*)d_out;

    const int n = in_sizes[0] / DM;
    const int E = in_sizes[3] / 2;

    static bool attr_set = false;
    if (!attr_set) {
        cudaFuncSetAttribute(fused_kernel, cudaFuncAttributeMaxDynamicSharedMemorySize, SMEM_BYTES);
        attr_set = true;
    }

    prologue_kernel<<<16, 256>>>(W, b);
    fused_kernel<<<(n + TILE - 1) / TILE, 256, SMEM_BYTES>>>(x, ei, out, n, E);
}